// round 8
// baseline (speedup 1.0000x reference)
#include <cuda_runtime.h>
#include <cuda_bf16.h>
#include <math.h>
#include <stdint.h>

// Problem constants
#define BB   8
#define SS   1024
#define DD   1024
#define HH   16
#define KD   64
#define VD   64
#define MTOT (BB*SS)             // 8192
#define NELEM_PER_BATCH (SS*DD)  // 1048576

// ---------------------------------------------------------------------------
// Scratch (device globals; no dynamic allocation allowed)
// ---------------------------------------------------------------------------
__device__ float g_Q[(size_t)BB*HH*SS*KD];    // [b,h,s,kd]  32 MiB
__device__ float g_K[(size_t)BB*HH*SS*KD];    // [b,h,s,kd]  32 MiB
__device__ float g_V[(size_t)BB*HH*SS*VD];    // [b,h,s,vd]  32 MiB
__device__ float g_Ctx[(size_t)MTOT*DD];      // [m, h*64+vd] 32 MiB
__device__ float g_Y[(size_t)MTOT*DD];        // pre-LN y     32 MiB
__device__ float g_psum[512];
__device__ float g_psq[512];
__device__ float g_mean[BB];
__device__ float g_rstd[BB];

// ---------------------------------------------------------------------------
// Numeric helpers
// ---------------------------------------------------------------------------
__device__ __forceinline__ float f2tf(float f) {
    uint32_t u;
    asm("cvt.rna.tf32.f32 %0, %1;" : "=r"(u) : "f"(f));
    return __uint_as_float(u);
}
__device__ __forceinline__ float4 f2tf4(float4 v) {
    v.x = f2tf(v.x); v.y = f2tf(v.y); v.z = f2tf(v.z); v.w = f2tf(v.w);
    return v;
}
// pack two floats into bf16x2 (lo in low half)
__device__ __forceinline__ uint32_t pack_bf2(float lo, float hi) {
    uint32_t r;
    asm("cvt.rn.bf16x2.f32 %0, %1, %2;" : "=r"(r) : "f"(hi), "f"(lo));
    return r;
}

__device__ __forceinline__ void mma_tf32(float* c, const uint32_t* a, const uint32_t* b) {
    asm volatile(
        "mma.sync.aligned.m16n8k8.row.col.f32.tf32.tf32.f32 "
        "{%0,%1,%2,%3}, {%4,%5,%6,%7}, {%8,%9}, {%0,%1,%2,%3};"
        : "+f"(c[0]), "+f"(c[1]), "+f"(c[2]), "+f"(c[3])
        : "r"(a[0]), "r"(a[1]), "r"(a[2]), "r"(a[3]), "r"(b[0]), "r"(b[1]));
}
__device__ __forceinline__ void mma_bf16(float* c, const uint32_t* a, const uint32_t* b) {
    asm volatile(
        "mma.sync.aligned.m16n8k16.row.col.f32.bf16.bf16.f32 "
        "{%0,%1,%2,%3}, {%4,%5,%6,%7}, {%8,%9}, {%0,%1,%2,%3};"
        : "+f"(c[0]), "+f"(c[1]), "+f"(c[2]), "+f"(c[3])
        : "r"(a[0]), "r"(a[1]), "r"(a[2]), "r"(a[3]), "r"(b[0]), "r"(b[1]));
}
__device__ __forceinline__ void ldmat_x4(uint32_t& r0, uint32_t& r1, uint32_t& r2, uint32_t& r3,
                                         uint32_t addr) {
    asm volatile("ldmatrix.sync.aligned.m8n8.x4.shared.b16 {%0,%1,%2,%3}, [%4];"
                 : "=r"(r0), "=r"(r1), "=r"(r2), "=r"(r3) : "r"(addr));
}

// ---------------------------------------------------------------------------
// bf16 tensor-core GEMM: C[m,n] = sum_k A[m,k] * W[n,k] (+ epilogue)
//   128x128 tile, BK=16. 8 warps, warp tile 64x32 (4mt x 4nt of m16n8k16).
//   smem rows padded to 24 bf16 (48B): ldmatrix addrs 12r mod 32 hit all
//   banks once -> conflict-free; STS.128 phases likewise.
//   EPI 0: QK proj -> scatter g_Q/g_K (+bias)
//   EPI 1: V  proj -> scatter g_V (+bias)
//   EPI 2: O  proj -> +bias +residual -> g_Y, CTA partial sum/sumsq
// ---------------------------------------------------------------------------
#define BSTR 24   // bf16 elems per smem row (48 bytes)

template<int EPI>
__global__ __launch_bounds__(256, 2)
void gemm_bf16(const float* __restrict__ X, const float* __restrict__ W,
               const float* __restrict__ bias)
{
    __shared__ __nv_bfloat16 As[128][BSTR];
    __shared__ __nv_bfloat16 Bs[128][BSTR];
    __shared__ float rs[256];
    __shared__ float rq[256];

    const int tid = threadIdx.x;
    const int bm  = blockIdx.y * 128;
    const int bn  = blockIdx.x * 128;

    const float* A = (EPI == 2) ? g_Ctx : X;

    // Loader: thread -> (row = tid&127, khalf = tid>>7); loads 8 fp32, stores 8 bf16
    const int arow  = tid & 127;
    const int khalf = tid >> 7;                    // 0/1 -> k offset 8
    const float4* aptr = (const float4*)(A + (size_t)(bm + arow) * 1024 + khalf * 8);
    const float4* bptr = (const float4*)(W + (size_t)(bn + arow) * 1024 + khalf * 8);
    const uint32_t as_w = (uint32_t)__cvta_generic_to_shared(&As[arow][khalf * 8]);
    const uint32_t bs_w = (uint32_t)__cvta_generic_to_shared(&Bs[arow][khalf * 8]);

    // MMA mapping
    const int warp = tid >> 5;
    const int lane = tid & 31;
    const int wm   = (warp >> 2) * 64;   // 0 or 64
    const int wn   = (warp & 3) * 32;    // 0..96
    const int gid  = lane >> 2;
    const int tig  = lane & 3;

    // ldmatrix lane addresses (constant across k-tiles; smem single-buffered)
    const uint32_t as_base = (uint32_t)__cvta_generic_to_shared(&As[0][0]);
    const uint32_t bs_base = (uint32_t)__cvta_generic_to_shared(&Bs[0][0]);
    uint32_t a_rd[4], b_rd[2];
#pragma unroll
    for (int mt = 0; mt < 4; mt++) {
        const int row  = wm + mt * 16 + (lane & 15);
        const int koff = (lane >> 4) * 16;           // bytes (k 0..7 vs 8..15)
        a_rd[mt] = as_base + row * (BSTR * 2) + koff;
    }
#pragma unroll
    for (int np = 0; np < 2; np++) {
        const int n    = wn + np * 16 + ((lane >> 4) * 8) + (lane & 7);
        const int koff = ((lane >> 3) & 1) * 16;
        b_rd[np] = bs_base + n * (BSTR * 2) + koff;
    }

    float acc[4][4][4];
#pragma unroll
    for (int mt = 0; mt < 4; mt++)
#pragma unroll
        for (int nt = 0; nt < 4; nt++)
#pragma unroll
            for (int e = 0; e < 4; e++) acc[mt][nt][e] = 0.f;

    float4 a0 = aptr[0], a1 = aptr[1];
    float4 b0 = bptr[0], b1 = bptr[1];

#pragma unroll 1
    for (int kt = 0; kt < 1024; kt += 16) {
        // store prefetched slab as bf16
        {
            uint32_t p0 = pack_bf2(a0.x, a0.y), p1 = pack_bf2(a0.z, a0.w);
            uint32_t p2 = pack_bf2(a1.x, a1.y), p3 = pack_bf2(a1.z, a1.w);
            asm volatile("st.shared.v4.b32 [%0], {%1,%2,%3,%4};"
                         :: "r"(as_w), "r"(p0), "r"(p1), "r"(p2), "r"(p3));
            p0 = pack_bf2(b0.x, b0.y); p1 = pack_bf2(b0.z, b0.w);
            p2 = pack_bf2(b1.x, b1.y); p3 = pack_bf2(b1.z, b1.w);
            asm volatile("st.shared.v4.b32 [%0], {%1,%2,%3,%4};"
                         :: "r"(bs_w), "r"(p0), "r"(p1), "r"(p2), "r"(p3));
        }
        __syncthreads();

        if (kt + 16 < 1024) {   // prefetch next slab
            const int f4 = (kt + 16) >> 2;
            a0 = aptr[f4]; a1 = aptr[f4 + 1];
            b0 = bptr[f4]; b1 = bptr[f4 + 1];
        }

        uint32_t af[4][4];
        uint32_t bf[4][2];
#pragma unroll
        for (int mt = 0; mt < 4; mt++)
            ldmat_x4(af[mt][0], af[mt][1], af[mt][2], af[mt][3], a_rd[mt]);
#pragma unroll
        for (int np = 0; np < 2; np++) {
            uint32_t t0, t1, t2, t3;
            ldmat_x4(t0, t1, t2, t3, b_rd[np]);
            bf[np*2    ][0] = t0; bf[np*2    ][1] = t1;
            bf[np*2 + 1][0] = t2; bf[np*2 + 1][1] = t3;
        }
#pragma unroll
        for (int mt = 0; mt < 4; mt++)
#pragma unroll
            for (int nt = 0; nt < 4; nt++)
                mma_bf16(acc[mt][nt], af[mt], bf[nt]);
        __syncthreads();
    }

    // ---------------- epilogue (fp32 acc; same mapping as tf32 version) ----
    float lsum = 0.f, lsq = 0.f;
#pragma unroll
    for (int mt = 0; mt < 4; mt++) {
#pragma unroll
        for (int e2 = 0; e2 < 2; e2++) {
            const int m    = bm + wm + mt * 16 + gid + e2 * 8;
            const int bidx = m >> 10;
            const int si   = m & 1023;
#pragma unroll
            for (int nt = 0; nt < 4; nt++) {
#pragma unroll
                for (int e1 = 0; e1 < 2; e1++) {
                    const int n = bn + wn + nt * 8 + tig * 2 + e1;
                    float val = acc[mt][nt][e2 * 2 + e1] + bias[n];
                    if (EPI == 0) {
                        const int kd  = n >> 5;
                        const int rem = n & 31;
                        const int h   = rem & 15;
                        const size_t dst = (((size_t)bidx*HH + h)*SS + si)*KD + kd;
                        if (rem < 16) g_Q[dst] = val; else g_K[dst] = val;
                    } else if (EPI == 1) {
                        const int vd = n >> 4;
                        const int h  = n & 15;
                        g_V[(((size_t)bidx*HH + h)*SS + si)*VD + vd] = val;
                    } else {
                        val += X[(size_t)m*1024 + n];
                        g_Y[(size_t)m*1024 + n] = val;
                        lsum += val;
                        lsq  += val * val;
                    }
                }
            }
        }
    }

    if (EPI == 2) {
        rs[tid] = lsum; rq[tid] = lsq;
        __syncthreads();
#pragma unroll
        for (int s = 128; s > 0; s >>= 1) {
            if (tid < s) { rs[tid] += rs[tid+s]; rq[tid] += rq[tid+s]; }
            __syncthreads();
        }
        if (tid == 0) {
            const int p = blockIdx.y * 8 + blockIdx.x;
            g_psum[p] = rs[0];
            g_psq[p]  = rq[0];
        }
    }
}

// ---------------------------------------------------------------------------
// Tensor-core flash attention (unchanged from R5 passing version).
// CTA = (b, h, 64 q-rows), 128 threads; tf32 MMA, P in registers.
// ---------------------------------------------------------------------------
__global__ __launch_bounds__(128, 2)
void attn_mma()
{
    __shared__ float Ks[64][68];   // [key][kd]  (also Q staging)
    __shared__ float Vs[64][72];   // [key][vd]

    const int tid   = threadIdx.x;
    const int warp  = tid >> 5;
    const int lane  = tid & 31;
    const int gid   = lane >> 2;
    const int tig   = lane & 3;
    const int qbase = lane & ~3;

    const int qt = blockIdx.x;
    const int h  = blockIdx.y;
    const int b  = blockIdx.z;
    const size_t bh = ((size_t)b*HH + h) * SS * KD;
    const float* Qg = g_Q + bh + (size_t)qt*64*KD;
    const float* Kg = g_K + bh;
    const float* Vg = g_V + bh;

    const int lr = tid >> 1;
    const int lc = (tid & 1) * 8;

    {
        const float4* src = (const float4*)(Qg + (size_t)lr*KD);
#pragma unroll
        for (int i = 0; i < 8; i++) {
            float4 v = src[lc + i];
            v.x *= 0.125f; v.y *= 0.125f; v.z *= 0.125f; v.w *= 0.125f;
            *(float4*)&Ks[lr][(lc + i)*4] = f2tf4(v);
        }
    }
    __syncthreads();

    uint32_t qf[8][4];
    const int wq = warp * 16;
#pragma unroll
    for (int ks = 0; ks < 8; ks++) {
        qf[ks][0] = __float_as_uint(Ks[wq + gid    ][ks*8 + tig    ]);
        qf[ks][1] = __float_as_uint(Ks[wq + gid + 8][ks*8 + tig    ]);
        qf[ks][2] = __float_as_uint(Ks[wq + gid    ][ks*8 + tig + 4]);
        qf[ks][3] = __float_as_uint(Ks[wq + gid + 8][ks*8 + tig + 4]);
    }
    __syncthreads();

    {
        const float4* kp = (const float4*)(Kg + (size_t)lr*KD);
        const float4* vp = (const float4*)(Vg + (size_t)lr*KD);
#pragma unroll
        for (int i = 0; i < 8; i++) {
            *(float4*)&Ks[lr][(lc + i)*4] = f2tf4(kp[lc + i]);
            *(float4*)&Vs[lr][(lc + i)*4] = f2tf4(vp[lc + i]);
        }
    }
    __syncthreads();

    float mi[2] = {-1e30f, -1e30f};
    float li[2] = {0.f, 0.f};
    float o[8][4];
#pragma unroll
    for (int nt = 0; nt < 8; nt++)
#pragma unroll
        for (int e = 0; e < 4; e++) o[nt][e] = 0.f;

#pragma unroll 1
    for (int j = 0; j < 16; j++) {
        float4 kr[8], vr[8];
        if (j < 15) {
            const float4* kp = (const float4*)(Kg + (size_t)(j + 1)*64*KD + (size_t)lr*KD);
            const float4* vp = (const float4*)(Vg + (size_t)(j + 1)*64*KD + (size_t)lr*KD);
#pragma unroll
            for (int i = 0; i < 8; i++) { kr[i] = kp[lc + i]; vr[i] = vp[lc + i]; }
        }

        float sc[8][4];
#pragma unroll
        for (int nt = 0; nt < 8; nt++)
#pragma unroll
            for (int e = 0; e < 4; e++) sc[nt][e] = 0.f;

#pragma unroll
        for (int ks = 0; ks < 8; ks++) {
#pragma unroll
            for (int nt = 0; nt < 8; nt++) {
                uint32_t bf[2];
                bf[0] = __float_as_uint(Ks[nt*8 + gid][ks*8 + tig    ]);
                bf[1] = __float_as_uint(Ks[nt*8 + gid][ks*8 + tig + 4]);
                mma_tf32(sc[nt], qf[ks], bf);
            }
        }

        float mx0 = -1e30f, mx1 = -1e30f;
#pragma unroll
        for (int nt = 0; nt < 8; nt++) {
            mx0 = fmaxf(mx0, fmaxf(sc[nt][0], sc[nt][1]));
            mx1 = fmaxf(mx1, fmaxf(sc[nt][2], sc[nt][3]));
        }
        mx0 = fmaxf(mx0, __shfl_xor_sync(0xffffffffu, mx0, 1));
        mx0 = fmaxf(mx0, __shfl_xor_sync(0xffffffffu, mx0, 2));
        mx1 = fmaxf(mx1, __shfl_xor_sync(0xffffffffu, mx1, 1));
        mx1 = fmaxf(mx1, __shfl_xor_sync(0xffffffffu, mx1, 2));

        const float mn0 = fmaxf(mi[0], mx0);
        const float mn1 = fmaxf(mi[1], mx1);
        const float c0  = __expf(mi[0] - mn0);
        const float c1  = __expf(mi[1] - mn1);

        float s0 = 0.f, s1 = 0.f;
#pragma unroll
        for (int nt = 0; nt < 8; nt++) {
            sc[nt][0] = __expf(sc[nt][0] - mn0); s0 += sc[nt][0];
            sc[nt][1] = __expf(sc[nt][1] - mn0); s0 += sc[nt][1];
            sc[nt][2] = __expf(sc[nt][2] - mn1); s1 += sc[nt][2];
            sc[nt][3] = __expf(sc[nt][3] - mn1); s1 += sc[nt][3];
        }
        s0 += __shfl_xor_sync(0xffffffffu, s0, 1);
        s0 += __shfl_xor_sync(0xffffffffu, s0, 2);
        s1 += __shfl_xor_sync(0xffffffffu, s1, 1);
        s1 += __shfl_xor_sync(0xffffffffu, s1, 2);

        li[0] = li[0]*c0 + s0;
        li[1] = li[1]*c1 + s1;
        mi[0] = mn0; mi[1] = mn1;
#pragma unroll
        for (int nt = 0; nt < 8; nt++) {
            o[nt][0] *= c0; o[nt][1] *= c0;
            o[nt][2] *= c1; o[nt][3] *= c1;
        }

#pragma unroll
        for (int ks = 0; ks < 8; ks++) {
            const int src  = qbase + (tig >> 1);
            const int src2 = src + 2;
            const float v0 = __shfl_sync(0xffffffffu, sc[ks][0], src);
            const float v1 = __shfl_sync(0xffffffffu, sc[ks][1], src);
            const float x0 = __shfl_sync(0xffffffffu, sc[ks][2], src);
            const float x1 = __shfl_sync(0xffffffffu, sc[ks][3], src);
            const float w0 = __shfl_sync(0xffffffffu, sc[ks][0], src2);
            const float w1 = __shfl_sync(0xffffffffu, sc[ks][1], src2);
            const float y0 = __shfl_sync(0xffffffffu, sc[ks][2], src2);
            const float y1 = __shfl_sync(0xffffffffu, sc[ks][3], src2);
            uint32_t af[4];
            af[0] = __float_as_uint(f2tf((tig & 1) ? v1 : v0));
            af[1] = __float_as_uint(f2tf((tig & 1) ? x1 : x0));
            af[2] = __float_as_uint(f2tf((tig & 1) ? w1 : w0));
            af[3] = __float_as_uint(f2tf((tig & 1) ? y1 : y0));
#pragma unroll
            for (int nt = 0; nt < 8; nt++) {
                uint32_t bf[2];
                bf[0] = __float_as_uint(Vs[ks*8 + tig    ][nt*8 + gid]);
                bf[1] = __float_as_uint(Vs[ks*8 + tig + 4][nt*8 + gid]);
                mma_tf32(o[nt], af, bf);
            }
        }

        __syncthreads();
        if (j < 15) {
#pragma unroll
            for (int i = 0; i < 8; i++) {
                *(float4*)&Ks[lr][(lc + i)*4] = f2tf4(kr[i]);
                *(float4*)&Vs[lr][(lc + i)*4] = f2tf4(vr[i]);
            }
        }
        __syncthreads();
    }

    const float inv0 = 1.0f / li[0];
    const float inv1 = 1.0f / li[1];
    const int r0 = qt*64 + wq + gid;
    const int r1 = r0 + 8;
#pragma unroll
    for (int nt = 0; nt < 8; nt++) {
        const int col = h*64 + nt*8 + tig*2;
        float2 u0 = make_float2(o[nt][0]*inv0, o[nt][1]*inv0);
        float2 u1 = make_float2(o[nt][2]*inv1, o[nt][3]*inv1);
        *(float2*)&g_Ctx[((size_t)(b*SS + r0))*DD + col] = u0;
        *(float2*)&g_Ctx[((size_t)(b*SS + r1))*DD + col] = u1;
    }
}

// ---------------------------------------------------------------------------
__global__ void finalize_stats()
{
    const int t = threadIdx.x;
    if (t < BB) {
        double s = 0.0, q = 0.0;
        for (int i = 0; i < 64; i++) {
            s += (double)g_psum[t*64 + i];
            q += (double)g_psq [t*64 + i];
        }
        const double n = (double)NELEM_PER_BATCH;
        const double mean = s / n;
        const double var  = q / n - mean*mean;
        g_mean[t] = (float)mean;
        g_rstd[t] = (float)(1.0 / sqrt(var + 1e-5));
    }
}

__global__ __launch_bounds__(512)
void ln_apply(const float* __restrict__ lnw, const float* __restrict__ lnb,
              float* __restrict__ out)
{
    const size_t i4 = (size_t)blockIdx.x * 512 + threadIdx.x;
    const size_t i  = i4 * 4;
    const int b     = (int)(i >> 20);
    const size_t sd = i & (size_t)(NELEM_PER_BATCH - 1);

    const float4 y = *(const float4*)&g_Y[i];
    const float4 w = *(const float4*)&lnw[sd];
    const float4 c = *(const float4*)&lnb[sd];
    const float mu = g_mean[b];
    const float rs = g_rstd[b];

    float4 r;
    r.x = (y.x - mu)*rs*w.x + c.x;
    r.y = (y.y - mu)*rs*w.y + c.y;
    r.z = (y.z - mu)*rs*w.z + c.z;
    r.w = (y.w - mu)*rs*w.w + c.w;
    *(float4*)&out[i] = r;
}

// ---------------------------------------------------------------------------
extern "C" void kernel_launch(void* const* d_in, const int* in_sizes, int n_in,
                              void* d_out, int out_size)
{
    const float* x   = (const float*)d_in[0];
    const float* Wqk = (const float*)d_in[1];
    const float* bqk = (const float*)d_in[2];
    const float* Wv  = (const float*)d_in[3];
    const float* bv  = (const float*)d_in[4];
    const float* Wo  = (const float*)d_in[5];
    const float* bo  = (const float*)d_in[6];
    const float* lnw = (const float*)d_in[7];
    const float* lnb = (const float*)d_in[8];
    float* out = (float*)d_out;

    gemm_bf16<0><<<dim3(2048/128, MTOT/128), 256>>>(x, Wqk, bqk);   // q,k proj
    gemm_bf16<1><<<dim3(1024/128, MTOT/128), 256>>>(x, Wv,  bv);    // v proj
    attn_mma    <<<dim3(SS/64, HH, BB), 128>>>();                   // context
    gemm_bf16<2><<<dim3(1024/128, MTOT/128), 256>>>(x, Wo,  bo);    // y + stats
    finalize_stats<<<1, 32>>>();
    ln_apply<<<(MTOT*DD/4)/512, 512>>>(lnw, lnb, out);
}

// round 10
// speedup vs baseline: 1.4597x; 1.4597x over previous
#include <cuda_runtime.h>
#include <cuda_bf16.h>
#include <math.h>
#include <stdint.h>

// Problem constants
#define BB   8
#define SS   1024
#define DD   1024
#define HH   16
#define KD   64
#define VD   64
#define MTOT (BB*SS)             // 8192
#define NELEM_PER_BATCH (SS*DD)  // 1048576

// ---------------------------------------------------------------------------
// Scratch (device globals; no dynamic allocation allowed)
// ---------------------------------------------------------------------------
__device__ float g_Q[(size_t)BB*HH*SS*KD];          // [b,h,s,kd]  32 MiB
__device__ float g_K[(size_t)BB*HH*SS*KD];          // [b,h,s,kd]  32 MiB
__device__ float g_V[(size_t)BB*HH*SS*VD];          // [b,h,s,vd]  32 MiB
__device__ float g_Y[(size_t)MTOT*DD];              // pre-LN y    32 MiB
__device__ __nv_bfloat16 g_Xb  [(size_t)MTOT*DD];   // bf16 x      16 MiB
__device__ __nv_bfloat16 g_Ctxb[(size_t)MTOT*DD];   // bf16 ctx    16 MiB
__device__ __nv_bfloat16 g_Wqkb[(size_t)2048*DD];   // bf16 W_qk    4 MiB
__device__ __nv_bfloat16 g_Wvb [(size_t)1024*DD];   // bf16 W_v     2 MiB
__device__ __nv_bfloat16 g_Wob [(size_t)1024*DD];   // bf16 W_o     2 MiB
__device__ float g_psum[512];
__device__ float g_psq[512];
__device__ float g_mean[BB];
__device__ float g_rstd[BB];

// ---------------------------------------------------------------------------
// Numeric / MMA helpers
// ---------------------------------------------------------------------------
__device__ __forceinline__ float f2tf(float f) {
    uint32_t u;
    asm("cvt.rna.tf32.f32 %0, %1;" : "=r"(u) : "f"(f));
    return __uint_as_float(u);
}
__device__ __forceinline__ float4 f2tf4(float4 v) {
    v.x = f2tf(v.x); v.y = f2tf(v.y); v.z = f2tf(v.z); v.w = f2tf(v.w);
    return v;
}
__device__ __forceinline__ uint32_t pack_bf2(float lo, float hi) {
    uint32_t r;
    asm("cvt.rn.bf16x2.f32 %0, %1, %2;" : "=r"(r) : "f"(hi), "f"(lo));
    return r;
}
__device__ __forceinline__ void mma_tf32(float* c, const uint32_t* a, const uint32_t* b) {
    asm volatile(
        "mma.sync.aligned.m16n8k8.row.col.f32.tf32.tf32.f32 "
        "{%0,%1,%2,%3}, {%4,%5,%6,%7}, {%8,%9}, {%0,%1,%2,%3};"
        : "+f"(c[0]), "+f"(c[1]), "+f"(c[2]), "+f"(c[3])
        : "r"(a[0]), "r"(a[1]), "r"(a[2]), "r"(a[3]), "r"(b[0]), "r"(b[1]));
}
__device__ __forceinline__ void mma_bf16(float* c, const uint32_t* a, const uint32_t* b) {
    asm volatile(
        "mma.sync.aligned.m16n8k16.row.col.f32.bf16.bf16.f32 "
        "{%0,%1,%2,%3}, {%4,%5,%6,%7}, {%8,%9}, {%0,%1,%2,%3};"
        : "+f"(c[0]), "+f"(c[1]), "+f"(c[2]), "+f"(c[3])
        : "r"(a[0]), "r"(a[1]), "r"(a[2]), "r"(a[3]), "r"(b[0]), "r"(b[1]));
}
__device__ __forceinline__ void ldmat_x4(uint32_t& r0, uint32_t& r1, uint32_t& r2, uint32_t& r3,
                                         uint32_t addr) {
    asm volatile("ldmatrix.sync.aligned.m8n8.x4.shared.b16 {%0,%1,%2,%3}, [%4];"
                 : "=r"(r0), "=r"(r1), "=r"(r2), "=r"(r3) : "r"(addr));
}
#define CP_A16(dst, src) \
    asm volatile("cp.async.cg.shared.global [%0], [%1], 16;" :: "r"(dst), "l"(src))
#define CP_COMMIT() asm volatile("cp.async.commit_group;")
#define CP_WAIT1()  asm volatile("cp.async.wait_group 1;")

// ---------------------------------------------------------------------------
// fp32 -> bf16 conversion (bandwidth-bound; each thread 4 elems)
// ---------------------------------------------------------------------------
__global__ __launch_bounds__(256)
void convertk(const float* __restrict__ src, __nv_bfloat16* __restrict__ dst)
{
    const size_t i = (size_t)blockIdx.x * 256 + threadIdx.x;
    const float4 f = ((const float4*)src)[i];
    uint2 p;
    p.x = pack_bf2(f.x, f.y);
    p.y = pack_bf2(f.z, f.w);
    ((uint2*)dst)[i] = p;
}

// ---------------------------------------------------------------------------
// cp.async 3-stage pipelined bf16 GEMM: C[m,n] = sum_k A[m,k]*W[n,k] (+epi)
//   A,W bf16 in gmem. 128x128 tile, BK=32, 32 iters. 8 warps, warp 64x32.
//   smem: 3 stages x (A 8KB + B 8KB) = 48KB, 64B rows, SW64 swizzle
//   chunk' = chunk ^ ((row>>1)&3)  -> conflict-free ldmatrix; k-hi = addr^0x20.
// ---------------------------------------------------------------------------
#define STAGE_BYTES 16384

template<int EPI>
__global__ __launch_bounds__(256)
void gemm_cp(const __nv_bfloat16* __restrict__ Ab,
             const __nv_bfloat16* __restrict__ Wb,
             const float* __restrict__ bias,
             const float* __restrict__ X)
{
    __shared__ __align__(128) char smem[3 * STAGE_BYTES];

    const int tid = threadIdx.x;
    const int bm  = blockIdx.y * 128;
    const int bn  = blockIdx.x * 128;

    const uint32_t sbase = (uint32_t)__cvta_generic_to_shared(smem);

    // ---- loader mapping: thread -> (row = tid>>1, chunks {c0, c0+1}) ----
    const int arow = tid >> 1;           // 0..127
    const int ac0  = (tid & 1) * 2;      // 0 or 2
    const int asw  = (arow >> 1) & 3;
    const __nv_bfloat16* agp = Ab + (size_t)(bm + arow) * 1024 + ac0 * 8;
    const __nv_bfloat16* bgp = Wb + (size_t)(bn + arow) * 1024 + ac0 * 8;
    const uint32_t st0 = sbase + arow * 64 + ((ac0     ^ asw) * 16);
    const uint32_t st1 = sbase + arow * 64 + (((ac0+1) ^ asw) * 16);

    // ---- MMA mapping ----
    const int warp = tid >> 5;
    const int lane = tid & 31;
    const int wm   = (warp >> 2) * 64;   // 0 or 64
    const int wn   = (warp & 3) * 32;    // 0..96
    const int gid  = lane >> 2;
    const int tig  = lane & 3;

    uint32_t a_rd[4], b_rd[2];
#pragma unroll
    for (int mt = 0; mt < 4; mt++) {
        const int row = wm + mt * 16 + (lane & 15);
        const int ch  = (lane >> 4) ^ ((row >> 1) & 3);
        a_rd[mt] = sbase + row * 64 + ch * 16;
    }
#pragma unroll
    for (int np = 0; np < 2; np++) {
        const int row = wn + np * 16 + ((lane >> 4) * 8) + (lane & 7);
        const int ch  = ((lane >> 3) & 1) ^ ((row >> 1) & 3);
        b_rd[np] = sbase + 8192 + row * 64 + ch * 16;
    }

    float acc[4][4][4];
#pragma unroll
    for (int mt = 0; mt < 4; mt++)
#pragma unroll
        for (int nt = 0; nt < 4; nt++)
#pragma unroll
            for (int e = 0; e < 4; e++) acc[mt][nt][e] = 0.f;

    // ---- prologue: stages 0,1 ----
#pragma unroll
    for (int s = 0; s < 2; s++) {
        const uint32_t so = s * STAGE_BYTES;
        const __nv_bfloat16* ag = agp + s * 32;
        const __nv_bfloat16* bg = bgp + s * 32;
        CP_A16(st0 + so,        ag);
        CP_A16(st1 + so,        ag + 8);
        CP_A16(st0 + so + 8192, bg);
        CP_A16(st1 + so + 8192, bg + 8);
        CP_COMMIT();
    }

    int stage = 0;
#pragma unroll 1
    for (int i = 0; i < 32; i++) {
        CP_WAIT1();
        __syncthreads();

        // issue stage i+2 (overwrites stage computed at iter i-1; safe via sync)
        if (i + 2 < 32) {
            const uint32_t so = ((i + 2) % 3) * STAGE_BYTES;
            const __nv_bfloat16* ag = agp + (i + 2) * 32;
            const __nv_bfloat16* bg = bgp + (i + 2) * 32;
            CP_A16(st0 + so,        ag);
            CP_A16(st1 + so,        ag + 8);
            CP_A16(st0 + so + 8192, bg);
            CP_A16(st1 + so + 8192, bg + 8);
        }
        CP_COMMIT();

        const uint32_t so = stage * STAGE_BYTES;
#pragma unroll
        for (int ks = 0; ks < 2; ks++) {
            const uint32_t kx = ks * 32;
            uint32_t af[4][4];
            uint32_t bf[4][2];
#pragma unroll
            for (int mt = 0; mt < 4; mt++)
                ldmat_x4(af[mt][0], af[mt][1], af[mt][2], af[mt][3],
                         (a_rd[mt] + so) ^ kx);
#pragma unroll
            for (int np = 0; np < 2; np++) {
                uint32_t t0, t1, t2, t3;
                ldmat_x4(t0, t1, t2, t3, (b_rd[np] + so) ^ kx);
                bf[np*2    ][0] = t0; bf[np*2    ][1] = t1;
                bf[np*2 + 1][0] = t2; bf[np*2 + 1][1] = t3;
            }
#pragma unroll
            for (int mt = 0; mt < 4; mt++)
#pragma unroll
                for (int nt = 0; nt < 4; nt++)
                    mma_bf16(acc[mt][nt], af[mt], bf[nt]);
        }
        __syncthreads();
        stage = (stage + 1 == 3) ? 0 : stage + 1;
    }

    // ---------------- epilogue ----------------
    float lsum = 0.f, lsq = 0.f;
#pragma unroll
    for (int mt = 0; mt < 4; mt++) {
#pragma unroll
        for (int e2 = 0; e2 < 2; e2++) {
            const int m    = bm + wm + mt * 16 + gid + e2 * 8;
            const int bidx = m >> 10;
            const int si   = m & 1023;
#pragma unroll
            for (int nt = 0; nt < 4; nt++) {
#pragma unroll
                for (int e1 = 0; e1 < 2; e1++) {
                    const int n = bn + wn + nt * 8 + tig * 2 + e1;
                    float val = acc[mt][nt][e2 * 2 + e1] + bias[n];
                    if (EPI == 0) {
                        const int kd  = n >> 5;
                        const int rem = n & 31;
                        const int h   = rem & 15;
                        const size_t dst = (((size_t)bidx*HH + h)*SS + si)*KD + kd;
                        if (rem < 16) g_Q[dst] = val; else g_K[dst] = val;
                    } else if (EPI == 1) {
                        const int vd = n >> 4;
                        const int h  = n & 15;
                        g_V[(((size_t)bidx*HH + h)*SS + si)*VD + vd] = val;
                    } else {
                        val += X[(size_t)m*1024 + n];
                        g_Y[(size_t)m*1024 + n] = val;
                        lsum += val;
                        lsq  += val * val;
                    }
                }
            }
        }
    }

    if (EPI == 2) {
        float* rs = (float*)smem;         // alias stage buffers (free now)
        float* rq = rs + 256;
        rs[tid] = lsum; rq[tid] = lsq;
        __syncthreads();
#pragma unroll
        for (int s = 128; s > 0; s >>= 1) {
            if (tid < s) { rs[tid] += rs[tid+s]; rq[tid] += rq[tid+s]; }
            __syncthreads();
        }
        if (tid == 0) {
            const int p = blockIdx.y * 8 + blockIdx.x;   // grid (8,64)
            g_psum[p] = rs[0];
            g_psq[p]  = rq[0];
        }
    }
}

// ---------------------------------------------------------------------------
// Tensor-core flash attention (R5-verified), epilogue now writes bf16 Ctx.
// ---------------------------------------------------------------------------
__global__ __launch_bounds__(128, 2)
void attn_mma()
{
    __shared__ float Ks[64][68];
    __shared__ float Vs[64][72];

    const int tid   = threadIdx.x;
    const int warp  = tid >> 5;
    const int lane  = tid & 31;
    const int gid   = lane >> 2;
    const int tig   = lane & 3;
    const int qbase = lane & ~3;

    const int qt = blockIdx.x;
    const int h  = blockIdx.y;
    const int b  = blockIdx.z;
    const size_t bh = ((size_t)b*HH + h) * SS * KD;
    const float* Qg = g_Q + bh + (size_t)qt*64*KD;
    const float* Kg = g_K + bh;
    const float* Vg = g_V + bh;

    const int lr = tid >> 1;
    const int lc = (tid & 1) * 8;

    {
        const float4* src = (const float4*)(Qg + (size_t)lr*KD);
#pragma unroll
        for (int i = 0; i < 8; i++) {
            float4 v = src[lc + i];
            v.x *= 0.125f; v.y *= 0.125f; v.z *= 0.125f; v.w *= 0.125f;
            *(float4*)&Ks[lr][(lc + i)*4] = f2tf4(v);
        }
    }
    __syncthreads();

    uint32_t qf[8][4];
    const int wq = warp * 16;
#pragma unroll
    for (int ks = 0; ks < 8; ks++) {
        qf[ks][0] = __float_as_uint(Ks[wq + gid    ][ks*8 + tig    ]);
        qf[ks][1] = __float_as_uint(Ks[wq + gid + 8][ks*8 + tig    ]);
        qf[ks][2] = __float_as_uint(Ks[wq + gid    ][ks*8 + tig + 4]);
        qf[ks][3] = __float_as_uint(Ks[wq + gid + 8][ks*8 + tig + 4]);
    }
    __syncthreads();

    {
        const float4* kp = (const float4*)(Kg + (size_t)lr*KD);
        const float4* vp = (const float4*)(Vg + (size_t)lr*KD);
#pragma unroll
        for (int i = 0; i < 8; i++) {
            *(float4*)&Ks[lr][(lc + i)*4] = f2tf4(kp[lc + i]);
            *(float4*)&Vs[lr][(lc + i)*4] = f2tf4(vp[lc + i]);
        }
    }
    __syncthreads();

    float mi[2] = {-1e30f, -1e30f};
    float li[2] = {0.f, 0.f};
    float o[8][4];
#pragma unroll
    for (int nt = 0; nt < 8; nt++)
#pragma unroll
        for (int e = 0; e < 4; e++) o[nt][e] = 0.f;

#pragma unroll 1
    for (int j = 0; j < 16; j++) {
        float4 kr[8], vr[8];
        if (j < 15) {
            const float4* kp = (const float4*)(Kg + (size_t)(j + 1)*64*KD + (size_t)lr*KD);
            const float4* vp = (const float4*)(Vg + (size_t)(j + 1)*64*KD + (size_t)lr*KD);
#pragma unroll
            for (int i = 0; i < 8; i++) { kr[i] = kp[lc + i]; vr[i] = vp[lc + i]; }
        }

        float sc[8][4];
#pragma unroll
        for (int nt = 0; nt < 8; nt++)
#pragma unroll
            for (int e = 0; e < 4; e++) sc[nt][e] = 0.f;

#pragma unroll
        for (int ks = 0; ks < 8; ks++) {
#pragma unroll
            for (int nt = 0; nt < 8; nt++) {
                uint32_t bf[2];
                bf[0] = __float_as_uint(Ks[nt*8 + gid][ks*8 + tig    ]);
                bf[1] = __float_as_uint(Ks[nt*8 + gid][ks*8 + tig + 4]);
                mma_tf32(sc[nt], qf[ks], bf);
            }
        }

        float mx0 = -1e30f, mx1 = -1e30f;
#pragma unroll
        for (int nt = 0; nt < 8; nt++) {
            mx0 = fmaxf(mx0, fmaxf(sc[nt][0], sc[nt][1]));
            mx1 = fmaxf(mx1, fmaxf(sc[nt][2], sc[nt][3]));
        }
        mx0 = fmaxf(mx0, __shfl_xor_sync(0xffffffffu, mx0, 1));
        mx0 = fmaxf(mx0, __shfl_xor_sync(0xffffffffu, mx0, 2));
        mx1 = fmaxf(mx1, __shfl_xor_sync(0xffffffffu, mx1, 1));
        mx1 = fmaxf(mx1, __shfl_xor_sync(0xffffffffu, mx1, 2));

        const float mn0 = fmaxf(mi[0], mx0);
        const float mn1 = fmaxf(mi[1], mx1);
        const float c0  = __expf(mi[0] - mn0);
        const float c1  = __expf(mi[1] - mn1);

        float s0 = 0.f, s1 = 0.f;
#pragma unroll
        for (int nt = 0; nt < 8; nt++) {
            sc[nt][0] = __expf(sc[nt][0] - mn0); s0 += sc[nt][0];
            sc[nt][1] = __expf(sc[nt][1] - mn0); s0 += sc[nt][1];
            sc[nt][2] = __expf(sc[nt][2] - mn1); s1 += sc[nt][2];
            sc[nt][3] = __expf(sc[nt][3] - mn1); s1 += sc[nt][3];
        }
        s0 += __shfl_xor_sync(0xffffffffu, s0, 1);
        s0 += __shfl_xor_sync(0xffffffffu, s0, 2);
        s1 += __shfl_xor_sync(0xffffffffu, s1, 1);
        s1 += __shfl_xor_sync(0xffffffffu, s1, 2);

        li[0] = li[0]*c0 + s0;
        li[1] = li[1]*c1 + s1;
        mi[0] = mn0; mi[1] = mn1;
#pragma unroll
        for (int nt = 0; nt < 8; nt++) {
            o[nt][0] *= c0; o[nt][1] *= c0;
            o[nt][2] *= c1; o[nt][3] *= c1;
        }

#pragma unroll
        for (int ks = 0; ks < 8; ks++) {
            const int src  = qbase + (tig >> 1);
            const int src2 = src + 2;
            const float v0 = __shfl_sync(0xffffffffu, sc[ks][0], src);
            const float v1 = __shfl_sync(0xffffffffu, sc[ks][1], src);
            const float x0 = __shfl_sync(0xffffffffu, sc[ks][2], src);
            const float x1 = __shfl_sync(0xffffffffu, sc[ks][3], src);
            const float w0 = __shfl_sync(0xffffffffu, sc[ks][0], src2);
            const float w1 = __shfl_sync(0xffffffffu, sc[ks][1], src2);
            const float y0 = __shfl_sync(0xffffffffu, sc[ks][2], src2);
            const float y1 = __shfl_sync(0xffffffffu, sc[ks][3], src2);
            uint32_t af[4];
            af[0] = __float_as_uint(f2tf((tig & 1) ? v1 : v0));
            af[1] = __float_as_uint(f2tf((tig & 1) ? x1 : x0));
            af[2] = __float_as_uint(f2tf((tig & 1) ? w1 : w0));
            af[3] = __float_as_uint(f2tf((tig & 1) ? y1 : y0));
#pragma unroll
            for (int nt = 0; nt < 8; nt++) {
                uint32_t bf[2];
                bf[0] = __float_as_uint(Vs[ks*8 + tig    ][nt*8 + gid]);
                bf[1] = __float_as_uint(Vs[ks*8 + tig + 4][nt*8 + gid]);
                mma_tf32(o[nt], af, bf);
            }
        }

        __syncthreads();
        if (j < 15) {
#pragma unroll
            for (int i = 0; i < 8; i++) {
                *(float4*)&Ks[lr][(lc + i)*4] = f2tf4(kr[i]);
                *(float4*)&Vs[lr][(lc + i)*4] = f2tf4(vr[i]);
            }
        }
        __syncthreads();
    }

    // ---- epilogue: bf16 Ctx[b*1024+s][h*64+vd] ----
    const float inv0 = 1.0f / li[0];
    const float inv1 = 1.0f / li[1];
    const int r0 = qt*64 + wq + gid;
    const int r1 = r0 + 8;
#pragma unroll
    for (int nt = 0; nt < 8; nt++) {
        const int col = h*64 + nt*8 + tig*2;
        *(uint32_t*)&g_Ctxb[((size_t)(b*SS + r0))*DD + col] =
            pack_bf2(o[nt][0]*inv0, o[nt][1]*inv0);
        *(uint32_t*)&g_Ctxb[((size_t)(b*SS + r1))*DD + col] =
            pack_bf2(o[nt][2]*inv1, o[nt][3]*inv1);
    }
}

// ---------------------------------------------------------------------------
__global__ void finalize_stats()
{
    const int t = threadIdx.x;
    if (t < BB) {
        double s = 0.0, q = 0.0;
        for (int i = 0; i < 64; i++) {
            s += (double)g_psum[t*64 + i];
            q += (double)g_psq [t*64 + i];
        }
        const double n = (double)NELEM_PER_BATCH;
        const double mean = s / n;
        const double var  = q / n - mean*mean;
        g_mean[t] = (float)mean;
        g_rstd[t] = (float)(1.0 / sqrt(var + 1e-5));
    }
}

__global__ __launch_bounds__(512)
void ln_apply(const float* __restrict__ lnw, const float* __restrict__ lnb,
              float* __restrict__ out)
{
    const size_t i4 = (size_t)blockIdx.x * 512 + threadIdx.x;
    const size_t i  = i4 * 4;
    const int b     = (int)(i >> 20);
    const size_t sd = i & (size_t)(NELEM_PER_BATCH - 1);

    const float4 y = *(const float4*)&g_Y[i];
    const float4 w = *(const float4*)&lnw[sd];
    const float4 c = *(const float4*)&lnb[sd];
    const float mu = g_mean[b];
    const float rs = g_rstd[b];

    float4 r;
    r.x = (y.x - mu)*rs*w.x + c.x;
    r.y = (y.y - mu)*rs*w.y + c.y;
    r.z = (y.z - mu)*rs*w.z + c.z;
    r.w = (y.w - mu)*rs*w.w + c.w;
    *(float4*)&out[i] = r;
}

// ---------------------------------------------------------------------------
extern "C" void kernel_launch(void* const* d_in, const int* in_sizes, int n_in,
                              void* d_out, int out_size)
{
    const float* x   = (const float*)d_in[0];
    const float* Wqk = (const float*)d_in[1];
    const float* bqk = (const float*)d_in[2];
    const float* Wv  = (const float*)d_in[3];
    const float* bv  = (const float*)d_in[4];
    const float* Wo  = (const float*)d_in[5];
    const float* bo  = (const float*)d_in[6];
    const float* lnw = (const float*)d_in[7];
    const float* lnb = (const float*)d_in[8];
    float* out = (float*)d_out;

    __nv_bfloat16 *Xb, *Wqkb, *Wvb, *Wob, *Ctxb;
    cudaGetSymbolAddress((void**)&Xb,   g_Xb);
    cudaGetSymbolAddress((void**)&Wqkb, g_Wqkb);
    cudaGetSymbolAddress((void**)&Wvb,  g_Wvb);
    cudaGetSymbolAddress((void**)&Wob,  g_Wob);
    cudaGetSymbolAddress((void**)&Ctxb, g_Ctxb);

    // fp32 -> bf16 operand conversion (once per launch; ~15us total)
    convertk<<<(MTOT*DD/4)/256, 256>>>(x,   Xb);     // 8192 blocks
    convertk<<<(2048*DD/4)/256, 256>>>(Wqk, Wqkb);   // 2048 blocks
    convertk<<<(1024*DD/4)/256, 256>>>(Wv,  Wvb);    // 1024 blocks
    convertk<<<(1024*DD/4)/256, 256>>>(Wo,  Wob);    // 1024 blocks

    gemm_cp<0><<<dim3(2048/128, MTOT/128), 256>>>(Xb,   Wqkb, bqk, x);  // q,k
    gemm_cp<1><<<dim3(1024/128, MTOT/128), 256>>>(Xb,   Wvb,  bv,  x);  // v
    attn_mma   <<<dim3(SS/64, HH, BB), 128>>>();                        // ctx (bf16)
    gemm_cp<2><<<dim3(1024/128, MTOT/128), 256>>>(Ctxb, Wob,  bo,  x);  // y + stats
    finalize_stats<<<1, 32>>>();
    ln_apply<<<(MTOT*DD/4)/512, 512>>>(lnw, lnb, out);
}

// round 11
// speedup vs baseline: 2.1631x; 1.4819x over previous
#include <cuda_runtime.h>
#include <cuda_bf16.h>
#include <math.h>
#include <stdint.h>

// Problem constants
#define BB   8
#define SS   1024
#define DD   1024
#define HH   16
#define KD   64
#define VD   64
#define MTOT (BB*SS)             // 8192
#define NELEM_PER_BATCH (SS*DD)  // 1048576

// ---------------------------------------------------------------------------
// Scratch (device globals; no dynamic allocation allowed)
// ---------------------------------------------------------------------------
__device__ __nv_bfloat16 g_Qb[(size_t)BB*HH*SS*KD];   // [b,h,s,kd] pre-scaled 1/8
__device__ __nv_bfloat16 g_Kb[(size_t)BB*HH*SS*KD];   // [b,h,s,kd]
__device__ __nv_bfloat16 g_Vb[(size_t)BB*HH*VD*SS];   // [b,h,vd,s]  TRANSPOSED
__device__ float g_Y[(size_t)MTOT*DD];                // pre-LN y    32 MiB
__device__ __nv_bfloat16 g_Xb  [(size_t)MTOT*DD];     // bf16 x      16 MiB
__device__ __nv_bfloat16 g_Ctxb[(size_t)MTOT*DD];     // bf16 ctx    16 MiB
__device__ __nv_bfloat16 g_Wqkb[(size_t)2048*DD];     // bf16 W_qk    4 MiB
__device__ __nv_bfloat16 g_Wvb [(size_t)1024*DD];     // bf16 W_v     2 MiB
__device__ __nv_bfloat16 g_Wob [(size_t)1024*DD];     // bf16 W_o     2 MiB
__device__ float g_psum[512];
__device__ float g_psq[512];
__device__ float g_mean[BB];
__device__ float g_rstd[BB];

// ---------------------------------------------------------------------------
// Numeric / MMA helpers
// ---------------------------------------------------------------------------
__device__ __forceinline__ uint32_t pack_bf2(float lo, float hi) {
    uint32_t r;
    asm("cvt.rn.bf16x2.f32 %0, %1, %2;" : "=r"(r) : "f"(hi), "f"(lo));
    return r;
}
__device__ __forceinline__ void mma_bf16(float* c, const uint32_t* a, const uint32_t* b) {
    asm volatile(
        "mma.sync.aligned.m16n8k16.row.col.f32.bf16.bf16.f32 "
        "{%0,%1,%2,%3}, {%4,%5,%6,%7}, {%8,%9}, {%0,%1,%2,%3};"
        : "+f"(c[0]), "+f"(c[1]), "+f"(c[2]), "+f"(c[3])
        : "r"(a[0]), "r"(a[1]), "r"(a[2]), "r"(a[3]), "r"(b[0]), "r"(b[1]));
}
__device__ __forceinline__ void ldmat_x4(uint32_t& r0, uint32_t& r1, uint32_t& r2, uint32_t& r3,
                                         uint32_t addr) {
    asm volatile("ldmatrix.sync.aligned.m8n8.x4.shared.b16 {%0,%1,%2,%3}, [%4];"
                 : "=r"(r0), "=r"(r1), "=r"(r2), "=r"(r3) : "r"(addr));
}
#define CP_A16(dst, src) \
    asm volatile("cp.async.cg.shared.global [%0], [%1], 16;" :: "r"(dst), "l"(src))
#define CP_COMMIT() asm volatile("cp.async.commit_group;")
#define CP_WAIT1()  asm volatile("cp.async.wait_group 1;")

// ---------------------------------------------------------------------------
// fp32 -> bf16 conversion
// ---------------------------------------------------------------------------
__global__ __launch_bounds__(256)
void convertk(const float* __restrict__ src, __nv_bfloat16* __restrict__ dst)
{
    const size_t i = (size_t)blockIdx.x * 256 + threadIdx.x;
    const float4 f = ((const float4*)src)[i];
    uint2 p;
    p.x = pack_bf2(f.x, f.y);
    p.y = pack_bf2(f.z, f.w);
    ((uint2*)dst)[i] = p;
}

// ---------------------------------------------------------------------------
// cp.async 3-stage pipelined bf16 GEMM (R10-verified): C = A @ W^T (+epi)
//   EPI 0: QK proj -> bf16 g_Qb (x0.125) / g_Kb
//   EPI 1: V  proj -> bf16 g_Vb TRANSPOSED [b,h,vd,s]
//   EPI 2: O  proj -> +bias +residual -> g_Y, partial sums
// ---------------------------------------------------------------------------
#define STAGE_BYTES 16384

template<int EPI>
__global__ __launch_bounds__(256)
void gemm_cp(const __nv_bfloat16* __restrict__ Ab,
             const __nv_bfloat16* __restrict__ Wb,
             const float* __restrict__ bias,
             const float* __restrict__ X)
{
    __shared__ __align__(128) char smem[3 * STAGE_BYTES];

    const int tid = threadIdx.x;
    const int bm  = blockIdx.y * 128;
    const int bn  = blockIdx.x * 128;

    const uint32_t sbase = (uint32_t)__cvta_generic_to_shared(smem);

    const int arow = tid >> 1;
    const int ac0  = (tid & 1) * 2;
    const int asw  = (arow >> 1) & 3;
    const __nv_bfloat16* agp = Ab + (size_t)(bm + arow) * 1024 + ac0 * 8;
    const __nv_bfloat16* bgp = Wb + (size_t)(bn + arow) * 1024 + ac0 * 8;
    const uint32_t st0 = sbase + arow * 64 + ((ac0     ^ asw) * 16);
    const uint32_t st1 = sbase + arow * 64 + (((ac0+1) ^ asw) * 16);

    const int warp = tid >> 5;
    const int lane = tid & 31;
    const int wm   = (warp >> 2) * 64;
    const int wn   = (warp & 3) * 32;
    const int gid  = lane >> 2;
    const int tig  = lane & 3;

    uint32_t a_rd[4], b_rd[2];
#pragma unroll
    for (int mt = 0; mt < 4; mt++) {
        const int row = wm + mt * 16 + (lane & 15);
        const int ch  = (lane >> 4) ^ ((row >> 1) & 3);
        a_rd[mt] = sbase + row * 64 + ch * 16;
    }
#pragma unroll
    for (int np = 0; np < 2; np++) {
        const int row = wn + np * 16 + ((lane >> 4) * 8) + (lane & 7);
        const int ch  = ((lane >> 3) & 1) ^ ((row >> 1) & 3);
        b_rd[np] = sbase + 8192 + row * 64 + ch * 16;
    }

    float acc[4][4][4];
#pragma unroll
    for (int mt = 0; mt < 4; mt++)
#pragma unroll
        for (int nt = 0; nt < 4; nt++)
#pragma unroll
            for (int e = 0; e < 4; e++) acc[mt][nt][e] = 0.f;

#pragma unroll
    for (int s = 0; s < 2; s++) {
        const uint32_t so = s * STAGE_BYTES;
        const __nv_bfloat16* ag = agp + s * 32;
        const __nv_bfloat16* bg = bgp + s * 32;
        CP_A16(st0 + so,        ag);
        CP_A16(st1 + so,        ag + 8);
        CP_A16(st0 + so + 8192, bg);
        CP_A16(st1 + so + 8192, bg + 8);
        CP_COMMIT();
    }

    int stage = 0;
#pragma unroll 1
    for (int i = 0; i < 32; i++) {
        CP_WAIT1();
        __syncthreads();

        if (i + 2 < 32) {
            const uint32_t so = ((i + 2) % 3) * STAGE_BYTES;
            const __nv_bfloat16* ag = agp + (i + 2) * 32;
            const __nv_bfloat16* bg = bgp + (i + 2) * 32;
            CP_A16(st0 + so,        ag);
            CP_A16(st1 + so,        ag + 8);
            CP_A16(st0 + so + 8192, bg);
            CP_A16(st1 + so + 8192, bg + 8);
        }
        CP_COMMIT();

        const uint32_t so = stage * STAGE_BYTES;
#pragma unroll
        for (int ks = 0; ks < 2; ks++) {
            const uint32_t kx = ks * 32;
            uint32_t af[4][4];
            uint32_t bf[4][2];
#pragma unroll
            for (int mt = 0; mt < 4; mt++)
                ldmat_x4(af[mt][0], af[mt][1], af[mt][2], af[mt][3],
                         (a_rd[mt] + so) ^ kx);
#pragma unroll
            for (int np = 0; np < 2; np++) {
                uint32_t t0, t1, t2, t3;
                ldmat_x4(t0, t1, t2, t3, (b_rd[np] + so) ^ kx);
                bf[np*2    ][0] = t0; bf[np*2    ][1] = t1;
                bf[np*2 + 1][0] = t2; bf[np*2 + 1][1] = t3;
            }
#pragma unroll
            for (int mt = 0; mt < 4; mt++)
#pragma unroll
                for (int nt = 0; nt < 4; nt++)
                    mma_bf16(acc[mt][nt], af[mt], bf[nt]);
        }
        __syncthreads();
        stage = (stage + 1 == 3) ? 0 : stage + 1;
    }

    // ---------------- epilogue ----------------
    float lsum = 0.f, lsq = 0.f;
#pragma unroll
    for (int mt = 0; mt < 4; mt++) {
#pragma unroll
        for (int e2 = 0; e2 < 2; e2++) {
            const int m    = bm + wm + mt * 16 + gid + e2 * 8;
            const int bidx = m >> 10;
            const int si   = m & 1023;
#pragma unroll
            for (int nt = 0; nt < 4; nt++) {
#pragma unroll
                for (int e1 = 0; e1 < 2; e1++) {
                    const int n = bn + wn + nt * 8 + tig * 2 + e1;
                    float val = acc[mt][nt][e2 * 2 + e1] + bias[n];
                    if (EPI == 0) {
                        const int kd  = n >> 5;
                        const int rem = n & 31;
                        const int h   = rem & 15;
                        const size_t dst = (((size_t)bidx*HH + h)*SS + si)*KD + kd;
                        if (rem < 16) g_Qb[dst] = __float2bfloat16(val * 0.125f);
                        else          g_Kb[dst] = __float2bfloat16(val);
                    } else if (EPI == 1) {
                        const int vd = n >> 4;
                        const int h  = n & 15;
                        g_Vb[(((size_t)bidx*HH + h)*VD + vd)*SS + si] =
                            __float2bfloat16(val);
                    } else {
                        val += X[(size_t)m*1024 + n];
                        g_Y[(size_t)m*1024 + n] = val;
                        lsum += val;
                        lsq  += val * val;
                    }
                }
            }
        }
    }

    if (EPI == 2) {
        float* rs = (float*)smem;
        float* rq = rs + 256;
        rs[tid] = lsum; rq[tid] = lsq;
        __syncthreads();
#pragma unroll
        for (int s = 128; s > 0; s >>= 1) {
            if (tid < s) { rs[tid] += rs[tid+s]; rq[tid] += rq[tid+s]; }
            __syncthreads();
        }
        if (tid == 0) {
            const int p = blockIdx.y * 8 + blockIdx.x;
            g_psum[p] = rs[0];
            g_psq[p]  = rq[0];
        }
    }
}

// ---------------------------------------------------------------------------
// Full-bf16 flash attention. CTA = (b,h, 64 q-rows), 128 threads (4 warps).
// S = QK^T and O += PV via m16n8k16 bf16 (fp32 accum). P never leaves
// registers: S C-frag layout == PV A-frag layout (pack_bf2 only).
//   Ks: [key][kd/2]  uint32 pairs, stride 36 -> banks 4*gid+tig (clean)
//   Vs: [vd][key/2]  uint32 pairs (V pre-transposed in gmem), stride 36
// ---------------------------------------------------------------------------
__global__ __launch_bounds__(128, 2)
void attn_bf16()
{
    __shared__ uint32_t Ks[64][36];   // K pairs; also Q staging
    __shared__ uint32_t Vs[64][36];   // V^T pairs

    const int tid  = threadIdx.x;
    const int warp = tid >> 5;
    const int lane = tid & 31;
    const int gid  = lane >> 2;
    const int tig  = lane & 3;

    const int qt = blockIdx.x;
    const int h  = blockIdx.y;
    const int b  = blockIdx.z;
    const size_t bh = (size_t)b*HH + h;
    const __nv_bfloat16* Qg = g_Qb + (bh*SS + (size_t)qt*64)*KD;
    const __nv_bfloat16* Kg = g_Kb + bh*SS*KD;
    const __nv_bfloat16* Vg = g_Vb + bh*VD*SS;     // [vd][s]

    const int lr = tid >> 1;          // 0..63
    const int lc = (tid & 1) * 4;     // uint4 idx base (8 per 128B row)

    // ---- stage Q (already scaled+bf16), grab A-frags ----
    {
        const uint4* src = (const uint4*)(Qg + (size_t)lr*KD);
#pragma unroll
        for (int i = 0; i < 4; i++)
            *(uint4*)&Ks[lr][(lc + i)*4] = src[lc + i];
    }
    __syncthreads();

    uint32_t qf[4][4];
    const int wq = warp * 16;
#pragma unroll
    for (int kc = 0; kc < 4; kc++) {
        qf[kc][0] = Ks[wq + gid    ][kc*8 + tig    ];
        qf[kc][1] = Ks[wq + gid + 8][kc*8 + tig    ];
        qf[kc][2] = Ks[wq + gid    ][kc*8 + tig + 4];
        qf[kc][3] = Ks[wq + gid + 8][kc*8 + tig + 4];
    }
    __syncthreads();

    // ---- first K/V tile ----
    {
        const uint4* kp = (const uint4*)(Kg + (size_t)lr*KD);
        const uint4* vp = (const uint4*)(Vg + (size_t)lr*SS);
#pragma unroll
        for (int i = 0; i < 4; i++) {
            *(uint4*)&Ks[lr][(lc + i)*4] = kp[lc + i];
            *(uint4*)&Vs[lr][(lc + i)*4] = vp[lc + i];
        }
    }
    __syncthreads();

    float mi[2] = {-1e30f, -1e30f};
    float li[2] = {0.f, 0.f};
    float o[8][4];
#pragma unroll
    for (int nt = 0; nt < 8; nt++)
#pragma unroll
        for (int e = 0; e < 4; e++) o[nt][e] = 0.f;

#pragma unroll 1
    for (int j = 0; j < 16; j++) {
        // register-prefetch next tile
        uint4 kr[4], vr[4];
        if (j < 15) {
            const uint4* kp = (const uint4*)(Kg + ((size_t)(j+1)*64 + lr)*KD);
            const uint4* vp = (const uint4*)(Vg + (size_t)lr*SS + (j+1)*64);
#pragma unroll
            for (int i = 0; i < 4; i++) { kr[i] = kp[lc + i]; vr[i] = vp[lc + i]; }
        }

        // ---- S = Q K^T : 4 kd-chunks x 8 key-tiles ----
        float sc[8][4];
#pragma unroll
        for (int nt = 0; nt < 8; nt++)
#pragma unroll
            for (int e = 0; e < 4; e++) sc[nt][e] = 0.f;

#pragma unroll
        for (int kc = 0; kc < 4; kc++) {
#pragma unroll
            for (int nt = 0; nt < 8; nt++) {
                uint32_t bf[2];
                bf[0] = Ks[nt*8 + gid][kc*8 + tig    ];
                bf[1] = Ks[nt*8 + gid][kc*8 + tig + 4];
                mma_bf16(sc[nt], qf[kc], bf);
            }
        }

        // ---- online softmax (rows gid / gid+8; quad reduction) ----
        float mx0 = -1e30f, mx1 = -1e30f;
#pragma unroll
        for (int nt = 0; nt < 8; nt++) {
            mx0 = fmaxf(mx0, fmaxf(sc[nt][0], sc[nt][1]));
            mx1 = fmaxf(mx1, fmaxf(sc[nt][2], sc[nt][3]));
        }
        mx0 = fmaxf(mx0, __shfl_xor_sync(0xffffffffu, mx0, 1));
        mx0 = fmaxf(mx0, __shfl_xor_sync(0xffffffffu, mx0, 2));
        mx1 = fmaxf(mx1, __shfl_xor_sync(0xffffffffu, mx1, 1));
        mx1 = fmaxf(mx1, __shfl_xor_sync(0xffffffffu, mx1, 2));

        const float mn0 = fmaxf(mi[0], mx0);
        const float mn1 = fmaxf(mi[1], mx1);
        const float c0  = __expf(mi[0] - mn0);
        const float c1  = __expf(mi[1] - mn1);

        float s0 = 0.f, s1 = 0.f;
#pragma unroll
        for (int nt = 0; nt < 8; nt++) {
            sc[nt][0] = __expf(sc[nt][0] - mn0); s0 += sc[nt][0];
            sc[nt][1] = __expf(sc[nt][1] - mn0); s0 += sc[nt][1];
            sc[nt][2] = __expf(sc[nt][2] - mn1); s1 += sc[nt][2];
            sc[nt][3] = __expf(sc[nt][3] - mn1); s1 += sc[nt][3];
        }
        s0 += __shfl_xor_sync(0xffffffffu, s0, 1);
        s0 += __shfl_xor_sync(0xffffffffu, s0, 2);
        s1 += __shfl_xor_sync(0xffffffffu, s1, 1);
        s1 += __shfl_xor_sync(0xffffffffu, s1, 2);

        li[0] = li[0]*c0 + s0;
        li[1] = li[1]*c1 + s1;
        mi[0] = mn0; mi[1] = mn1;
#pragma unroll
        for (int nt = 0; nt < 8; nt++) {
            o[nt][0] *= c0; o[nt][1] *= c0;
            o[nt][2] *= c1; o[nt][3] *= c1;
        }

        // ---- O += P V : P A-frags straight from sc registers ----
#pragma unroll
        for (int kc = 0; kc < 4; kc++) {
            uint32_t af[4];
            af[0] = pack_bf2(sc[2*kc    ][0], sc[2*kc    ][1]);  // row gid,   keys 16kc+2tig..
            af[1] = pack_bf2(sc[2*kc    ][2], sc[2*kc    ][3]);  // row gid+8
            af[2] = pack_bf2(sc[2*kc + 1][0], sc[2*kc + 1][1]);  // row gid,   keys +8
            af[3] = pack_bf2(sc[2*kc + 1][2], sc[2*kc + 1][3]);  // row gid+8, keys +8
#pragma unroll
            for (int nt = 0; nt < 8; nt++) {
                uint32_t bf[2];
                bf[0] = Vs[nt*8 + gid][kc*8 + tig    ];
                bf[1] = Vs[nt*8 + gid][kc*8 + tig + 4];
                mma_bf16(o[nt], af, bf);
            }
        }

        __syncthreads();
        if (j < 15) {
#pragma unroll
            for (int i = 0; i < 4; i++) {
                *(uint4*)&Ks[lr][(lc + i)*4] = kr[i];
                *(uint4*)&Vs[lr][(lc + i)*4] = vr[i];
            }
        }
        __syncthreads();
    }

    // ---- epilogue: bf16 Ctx[b*1024+s][h*64+vd] ----
    const float inv0 = 1.0f / li[0];
    const float inv1 = 1.0f / li[1];
    const int r0 = qt*64 + wq + gid;
    const int r1 = r0 + 8;
#pragma unroll
    for (int nt = 0; nt < 8; nt++) {
        const int col = h*64 + nt*8 + tig*2;
        *(uint32_t*)&g_Ctxb[((size_t)(b*SS + r0))*DD + col] =
            pack_bf2(o[nt][0]*inv0, o[nt][1]*inv0);
        *(uint32_t*)&g_Ctxb[((size_t)(b*SS + r1))*DD + col] =
            pack_bf2(o[nt][2]*inv1, o[nt][3]*inv1);
    }
}

// ---------------------------------------------------------------------------
__global__ void finalize_stats()
{
    const int t = threadIdx.x;
    if (t < BB) {
        double s = 0.0, q = 0.0;
        for (int i = 0; i < 64; i++) {
            s += (double)g_psum[t*64 + i];
            q += (double)g_psq [t*64 + i];
        }
        const double n = (double)NELEM_PER_BATCH;
        const double mean = s / n;
        const double var  = q / n - mean*mean;
        g_mean[t] = (float)mean;
        g_rstd[t] = (float)(1.0 / sqrt(var + 1e-5));
    }
}

__global__ __launch_bounds__(512)
void ln_apply(const float* __restrict__ lnw, const float* __restrict__ lnb,
              float* __restrict__ out)
{
    const size_t i4 = (size_t)blockIdx.x * 512 + threadIdx.x;
    const size_t i  = i4 * 4;
    const int b     = (int)(i >> 20);
    const size_t sd = i & (size_t)(NELEM_PER_BATCH - 1);

    const float4 y = *(const float4*)&g_Y[i];
    const float4 w = *(const float4*)&lnw[sd];
    const float4 c = *(const float4*)&lnb[sd];
    const float mu = g_mean[b];
    const float rs = g_rstd[b];

    float4 r;
    r.x = (y.x - mu)*rs*w.x + c.x;
    r.y = (y.y - mu)*rs*w.y + c.y;
    r.z = (y.z - mu)*rs*w.z + c.z;
    r.w = (y.w - mu)*rs*w.w + c.w;
    *(float4*)&out[i] = r;
}

// ---------------------------------------------------------------------------
extern "C" void kernel_launch(void* const* d_in, const int* in_sizes, int n_in,
                              void* d_out, int out_size)
{
    const float* x   = (const float*)d_in[0];
    const float* Wqk = (const float*)d_in[1];
    const float* bqk = (const float*)d_in[2];
    const float* Wv  = (const float*)d_in[3];
    const float* bv  = (const float*)d_in[4];
    const float* Wo  = (const float*)d_in[5];
    const float* bo  = (const float*)d_in[6];
    const float* lnw = (const float*)d_in[7];
    const float* lnb = (const float*)d_in[8];
    float* out = (float*)d_out;

    __nv_bfloat16 *Xb, *Wqkb, *Wvb, *Wob, *Ctxb;
    cudaGetSymbolAddress((void**)&Xb,   g_Xb);
    cudaGetSymbolAddress((void**)&Wqkb, g_Wqkb);
    cudaGetSymbolAddress((void**)&Wvb,  g_Wvb);
    cudaGetSymbolAddress((void**)&Wob,  g_Wob);
    cudaGetSymbolAddress((void**)&Ctxb, g_Ctxb);

    convertk<<<(MTOT*DD/4)/256, 256>>>(x,   Xb);
    convertk<<<(2048*DD/4)/256, 256>>>(Wqk, Wqkb);
    convertk<<<(1024*DD/4)/256, 256>>>(Wv,  Wvb);
    convertk<<<(1024*DD/4)/256, 256>>>(Wo,  Wob);

    gemm_cp<0><<<dim3(2048/128, MTOT/128), 256>>>(Xb,   Wqkb, bqk, x);  // q,k (bf16 out)
    gemm_cp<1><<<dim3(1024/128, MTOT/128), 256>>>(Xb,   Wvb,  bv,  x);  // v (transposed bf16)
    attn_bf16  <<<dim3(SS/64, HH, BB), 128>>>();                        // ctx (bf16)
    gemm_cp<2><<<dim3(1024/128, MTOT/128), 256>>>(Ctxb, Wob,  bo,  x);  // y + stats
    finalize_stats<<<1, 32>>>();
    ln_apply<<<(MTOT*DD/4)/512, 512>>>(lnw, lnb, out);
}

// round 12
// speedup vs baseline: 2.2552x; 1.0426x over previous
#include <cuda_runtime.h>
#include <cuda_bf16.h>
#include <math.h>
#include <stdint.h>

// Problem constants
#define BB   8
#define SS   1024
#define DD   1024
#define HH   16
#define KD   64
#define VD   64
#define MTOT (BB*SS)             // 8192
#define NELEM_PER_BATCH (SS*DD)  // 1048576

// ---------------------------------------------------------------------------
// Scratch (device globals; no dynamic allocation allowed)
// ---------------------------------------------------------------------------
__device__ __nv_bfloat16 g_Qb[(size_t)BB*HH*SS*KD];   // [b,h,s,kd] pre-scaled 1/8
__device__ __nv_bfloat16 g_Kb[(size_t)BB*HH*SS*KD];   // [b,h,s,kd]
__device__ __nv_bfloat16 g_Vb[(size_t)BB*HH*VD*SS];   // [b,h,vd,s]  TRANSPOSED
__device__ float g_Y[(size_t)MTOT*DD];                // pre-LN y    32 MiB
__device__ __nv_bfloat16 g_Xb  [(size_t)MTOT*DD];     // bf16 x      16 MiB
__device__ __nv_bfloat16 g_Ctxb[(size_t)MTOT*DD];     // bf16 ctx    16 MiB
__device__ __nv_bfloat16 g_Wqkb[(size_t)2048*DD];     // bf16 W_qk    4 MiB
__device__ __nv_bfloat16 g_Wvb [(size_t)1024*DD];     // bf16 W_v     2 MiB
__device__ __nv_bfloat16 g_Wob [(size_t)1024*DD];     // bf16 W_o     2 MiB
__device__ float g_psum[512];
__device__ float g_psq[512];
__device__ float g_mean[BB];
__device__ float g_rstd[BB];

// ---------------------------------------------------------------------------
// Numeric / MMA helpers
// ---------------------------------------------------------------------------
__device__ __forceinline__ uint32_t pack_bf2(float lo, float hi) {
    uint32_t r;
    asm("cvt.rn.bf16x2.f32 %0, %1, %2;" : "=r"(r) : "f"(hi), "f"(lo));
    return r;
}
__device__ __forceinline__ void mma_bf16(float* c, const uint32_t* a, const uint32_t* b) {
    asm volatile(
        "mma.sync.aligned.m16n8k16.row.col.f32.bf16.bf16.f32 "
        "{%0,%1,%2,%3}, {%4,%5,%6,%7}, {%8,%9}, {%0,%1,%2,%3};"
        : "+f"(c[0]), "+f"(c[1]), "+f"(c[2]), "+f"(c[3])
        : "r"(a[0]), "r"(a[1]), "r"(a[2]), "r"(a[3]), "r"(b[0]), "r"(b[1]));
}
__device__ __forceinline__ void ldmat_x4(uint32_t& r0, uint32_t& r1, uint32_t& r2, uint32_t& r3,
                                         uint32_t addr) {
    asm volatile("ldmatrix.sync.aligned.m8n8.x4.shared.b16 {%0,%1,%2,%3}, [%4];"
                 : "=r"(r0), "=r"(r1), "=r"(r2), "=r"(r3) : "r"(addr));
}
#define CP_A16(dst, src) \
    asm volatile("cp.async.cg.shared.global [%0], [%1], 16;" :: "r"(dst), "l"(src))
#define CP_COMMIT() asm volatile("cp.async.commit_group;")
#define CP_WAIT1()  asm volatile("cp.async.wait_group 1;")

// ---------------------------------------------------------------------------
// fp32 -> bf16 conversion
// ---------------------------------------------------------------------------
__global__ __launch_bounds__(256)
void convertk(const float* __restrict__ src, __nv_bfloat16* __restrict__ dst)
{
    const size_t i = (size_t)blockIdx.x * 256 + threadIdx.x;
    const float4 f = ((const float4*)src)[i];
    uint2 p;
    p.x = pack_bf2(f.x, f.y);
    p.y = pack_bf2(f.z, f.w);
    ((uint2*)dst)[i] = p;
}

// ---------------------------------------------------------------------------
// cp.async 3-stage pipelined bf16 GEMM: C = A @ W^T (+epi)
//   __launch_bounds__(256,2): cap regs at 128 -> 2 CTAs/SM (latency hiding).
//   ONE barrier per k-iteration: the leading sync at iter i implies all warps
//   finished iter i-1's compute -- the only readers of the slot that iter i's
//   cp.async overwrites ((i+2)%3 == (i-1)%3).
//   EPI 0: QK proj -> bf16 g_Qb (x0.125) / g_Kb
//   EPI 1: V  proj -> bf16 g_Vb TRANSPOSED [b,h,vd,s]
//   EPI 2: O  proj -> +bias +residual -> g_Y, partial sums
// ---------------------------------------------------------------------------
#define STAGE_BYTES 16384

template<int EPI>
__global__ __launch_bounds__(256, 2)
void gemm_cp(const __nv_bfloat16* __restrict__ Ab,
             const __nv_bfloat16* __restrict__ Wb,
             const float* __restrict__ bias,
             const float* __restrict__ X)
{
    __shared__ __align__(128) char smem[3 * STAGE_BYTES];

    const int tid = threadIdx.x;
    const int bm  = blockIdx.y * 128;
    const int bn  = blockIdx.x * 128;

    const uint32_t sbase = (uint32_t)__cvta_generic_to_shared(smem);

    const int arow = tid >> 1;
    const int ac0  = (tid & 1) * 2;
    const int asw  = (arow >> 1) & 3;
    const __nv_bfloat16* agp = Ab + (size_t)(bm + arow) * 1024 + ac0 * 8;
    const __nv_bfloat16* bgp = Wb + (size_t)(bn + arow) * 1024 + ac0 * 8;
    const uint32_t st0 = sbase + arow * 64 + ((ac0     ^ asw) * 16);
    const uint32_t st1 = sbase + arow * 64 + (((ac0+1) ^ asw) * 16);

    const int warp = tid >> 5;
    const int lane = tid & 31;
    const int wm   = (warp >> 2) * 64;
    const int wn   = (warp & 3) * 32;
    const int gid  = lane >> 2;
    const int tig  = lane & 3;

    uint32_t a_rd[4], b_rd[2];
#pragma unroll
    for (int mt = 0; mt < 4; mt++) {
        const int row = wm + mt * 16 + (lane & 15);
        const int ch  = (lane >> 4) ^ ((row >> 1) & 3);
        a_rd[mt] = sbase + row * 64 + ch * 16;
    }
#pragma unroll
    for (int np = 0; np < 2; np++) {
        const int row = wn + np * 16 + ((lane >> 4) * 8) + (lane & 7);
        const int ch  = ((lane >> 3) & 1) ^ ((row >> 1) & 3);
        b_rd[np] = sbase + 8192 + row * 64 + ch * 16;
    }

    float acc[4][4][4];
#pragma unroll
    for (int mt = 0; mt < 4; mt++)
#pragma unroll
        for (int nt = 0; nt < 4; nt++)
#pragma unroll
            for (int e = 0; e < 4; e++) acc[mt][nt][e] = 0.f;

#pragma unroll
    for (int s = 0; s < 2; s++) {
        const uint32_t so = s * STAGE_BYTES;
        const __nv_bfloat16* ag = agp + s * 32;
        const __nv_bfloat16* bg = bgp + s * 32;
        CP_A16(st0 + so,        ag);
        CP_A16(st1 + so,        ag + 8);
        CP_A16(st0 + so + 8192, bg);
        CP_A16(st1 + so + 8192, bg + 8);
        CP_COMMIT();
    }

    int stage = 0;
#pragma unroll 1
    for (int i = 0; i < 32; i++) {
        CP_WAIT1();
        __syncthreads();   // single barrier per iteration (see header comment)

        if (i + 2 < 32) {
            const uint32_t so = ((i + 2) % 3) * STAGE_BYTES;
            const __nv_bfloat16* ag = agp + (i + 2) * 32;
            const __nv_bfloat16* bg = bgp + (i + 2) * 32;
            CP_A16(st0 + so,        ag);
            CP_A16(st1 + so,        ag + 8);
            CP_A16(st0 + so + 8192, bg);
            CP_A16(st1 + so + 8192, bg + 8);
        }
        CP_COMMIT();

        const uint32_t so = stage * STAGE_BYTES;
#pragma unroll
        for (int ks = 0; ks < 2; ks++) {
            const uint32_t kx = ks * 32;
            uint32_t af[4][4];
            uint32_t bf[4][2];
#pragma unroll
            for (int mt = 0; mt < 4; mt++)
                ldmat_x4(af[mt][0], af[mt][1], af[mt][2], af[mt][3],
                         (a_rd[mt] + so) ^ kx);
#pragma unroll
            for (int np = 0; np < 2; np++) {
                uint32_t t0, t1, t2, t3;
                ldmat_x4(t0, t1, t2, t3, (b_rd[np] + so) ^ kx);
                bf[np*2    ][0] = t0; bf[np*2    ][1] = t1;
                bf[np*2 + 1][0] = t2; bf[np*2 + 1][1] = t3;
            }
#pragma unroll
            for (int mt = 0; mt < 4; mt++)
#pragma unroll
                for (int nt = 0; nt < 4; nt++)
                    mma_bf16(acc[mt][nt], af[mt], bf[nt]);
        }
        stage = (stage + 1 == 3) ? 0 : stage + 1;
    }

    // ---------------- epilogue ----------------
    float lsum = 0.f, lsq = 0.f;
#pragma unroll
    for (int mt = 0; mt < 4; mt++) {
#pragma unroll
        for (int e2 = 0; e2 < 2; e2++) {
            const int m    = bm + wm + mt * 16 + gid + e2 * 8;
            const int bidx = m >> 10;
            const int si   = m & 1023;
#pragma unroll
            for (int nt = 0; nt < 4; nt++) {
#pragma unroll
                for (int e1 = 0; e1 < 2; e1++) {
                    const int n = bn + wn + nt * 8 + tig * 2 + e1;
                    float val = acc[mt][nt][e2 * 2 + e1] + bias[n];
                    if (EPI == 0) {
                        const int kd  = n >> 5;
                        const int rem = n & 31;
                        const int h   = rem & 15;
                        const size_t dst = (((size_t)bidx*HH + h)*SS + si)*KD + kd;
                        if (rem < 16) g_Qb[dst] = __float2bfloat16(val * 0.125f);
                        else          g_Kb[dst] = __float2bfloat16(val);
                    } else if (EPI == 1) {
                        const int vd = n >> 4;
                        const int h  = n & 15;
                        g_Vb[(((size_t)bidx*HH + h)*VD + vd)*SS + si] =
                            __float2bfloat16(val);
                    } else {
                        val += X[(size_t)m*1024 + n];
                        g_Y[(size_t)m*1024 + n] = val;
                        lsum += val;
                        lsq  += val * val;
                    }
                }
            }
        }
    }

    if (EPI == 2) {
        float* rs = (float*)smem;     // stage-0 region; disjoint from stage-1
        float* rq = rs + 256;         // (last compute) and protected by the
        rs[tid] = lsum; rq[tid] = lsq;
        __syncthreads();              // reduction barrier before reads
#pragma unroll
        for (int s = 128; s > 0; s >>= 1) {
            if (tid < s) { rs[tid] += rs[tid+s]; rq[tid] += rq[tid+s]; }
            __syncthreads();
        }
        if (tid == 0) {
            const int p = blockIdx.y * 8 + blockIdx.x;
            g_psum[p] = rs[0];
            g_psq[p]  = rq[0];
        }
    }
}

// ---------------------------------------------------------------------------
// Full-bf16 flash attention (R11-verified). CTA = (b,h,64 q-rows), 128 thr.
// ---------------------------------------------------------------------------
__global__ __launch_bounds__(128, 2)
void attn_bf16()
{
    __shared__ uint32_t Ks[64][36];   // K pairs; also Q staging
    __shared__ uint32_t Vs[64][36];   // V^T pairs

    const int tid  = threadIdx.x;
    const int warp = tid >> 5;
    const int lane = tid & 31;
    const int gid  = lane >> 2;
    const int tig  = lane & 3;

    const int qt = blockIdx.x;
    const int h  = blockIdx.y;
    const int b  = blockIdx.z;
    const size_t bh = (size_t)b*HH + h;
    const __nv_bfloat16* Qg = g_Qb + (bh*SS + (size_t)qt*64)*KD;
    const __nv_bfloat16* Kg = g_Kb + bh*SS*KD;
    const __nv_bfloat16* Vg = g_Vb + bh*VD*SS;     // [vd][s]

    const int lr = tid >> 1;
    const int lc = (tid & 1) * 4;

    {
        const uint4* src = (const uint4*)(Qg + (size_t)lr*KD);
#pragma unroll
        for (int i = 0; i < 4; i++)
            *(uint4*)&Ks[lr][(lc + i)*4] = src[lc + i];
    }
    __syncthreads();

    uint32_t qf[4][4];
    const int wq = warp * 16;
#pragma unroll
    for (int kc = 0; kc < 4; kc++) {
        qf[kc][0] = Ks[wq + gid    ][kc*8 + tig    ];
        qf[kc][1] = Ks[wq + gid + 8][kc*8 + tig    ];
        qf[kc][2] = Ks[wq + gid    ][kc*8 + tig + 4];
        qf[kc][3] = Ks[wq + gid + 8][kc*8 + tig + 4];
    }
    __syncthreads();

    {
        const uint4* kp = (const uint4*)(Kg + (size_t)lr*KD);
        const uint4* vp = (const uint4*)(Vg + (size_t)lr*SS);
#pragma unroll
        for (int i = 0; i < 4; i++) {
            *(uint4*)&Ks[lr][(lc + i)*4] = kp[lc + i];
            *(uint4*)&Vs[lr][(lc + i)*4] = vp[lc + i];
        }
    }
    __syncthreads();

    float mi[2] = {-1e30f, -1e30f};
    float li[2] = {0.f, 0.f};
    float o[8][4];
#pragma unroll
    for (int nt = 0; nt < 8; nt++)
#pragma unroll
        for (int e = 0; e < 4; e++) o[nt][e] = 0.f;

#pragma unroll 1
    for (int j = 0; j < 16; j++) {
        uint4 kr[4], vr[4];
        if (j < 15) {
            const uint4* kp = (const uint4*)(Kg + ((size_t)(j+1)*64 + lr)*KD);
            const uint4* vp = (const uint4*)(Vg + (size_t)lr*SS + (j+1)*64);
#pragma unroll
            for (int i = 0; i < 4; i++) { kr[i] = kp[lc + i]; vr[i] = vp[lc + i]; }
        }

        float sc[8][4];
#pragma unroll
        for (int nt = 0; nt < 8; nt++)
#pragma unroll
            for (int e = 0; e < 4; e++) sc[nt][e] = 0.f;

#pragma unroll
        for (int kc = 0; kc < 4; kc++) {
#pragma unroll
            for (int nt = 0; nt < 8; nt++) {
                uint32_t bf[2];
                bf[0] = Ks[nt*8 + gid][kc*8 + tig    ];
                bf[1] = Ks[nt*8 + gid][kc*8 + tig + 4];
                mma_bf16(sc[nt], qf[kc], bf);
            }
        }

        float mx0 = -1e30f, mx1 = -1e30f;
#pragma unroll
        for (int nt = 0; nt < 8; nt++) {
            mx0 = fmaxf(mx0, fmaxf(sc[nt][0], sc[nt][1]));
            mx1 = fmaxf(mx1, fmaxf(sc[nt][2], sc[nt][3]));
        }
        mx0 = fmaxf(mx0, __shfl_xor_sync(0xffffffffu, mx0, 1));
        mx0 = fmaxf(mx0, __shfl_xor_sync(0xffffffffu, mx0, 2));
        mx1 = fmaxf(mx1, __shfl_xor_sync(0xffffffffu, mx1, 1));
        mx1 = fmaxf(mx1, __shfl_xor_sync(0xffffffffu, mx1, 2));

        const float mn0 = fmaxf(mi[0], mx0);
        const float mn1 = fmaxf(mi[1], mx1);
        const float c0  = __expf(mi[0] - mn0);
        const float c1  = __expf(mi[1] - mn1);

        float s0 = 0.f, s1 = 0.f;
#pragma unroll
        for (int nt = 0; nt < 8; nt++) {
            sc[nt][0] = __expf(sc[nt][0] - mn0); s0 += sc[nt][0];
            sc[nt][1] = __expf(sc[nt][1] - mn0); s0 += sc[nt][1];
            sc[nt][2] = __expf(sc[nt][2] - mn1); s1 += sc[nt][2];
            sc[nt][3] = __expf(sc[nt][3] - mn1); s1 += sc[nt][3];
        }
        s0 += __shfl_xor_sync(0xffffffffu, s0, 1);
        s0 += __shfl_xor_sync(0xffffffffu, s0, 2);
        s1 += __shfl_xor_sync(0xffffffffu, s1, 1);
        s1 += __shfl_xor_sync(0xffffffffu, s1, 2);

        li[0] = li[0]*c0 + s0;
        li[1] = li[1]*c1 + s1;
        mi[0] = mn0; mi[1] = mn1;
#pragma unroll
        for (int nt = 0; nt < 8; nt++) {
            o[nt][0] *= c0; o[nt][1] *= c0;
            o[nt][2] *= c1; o[nt][3] *= c1;
        }

#pragma unroll
        for (int kc = 0; kc < 4; kc++) {
            uint32_t af[4];
            af[0] = pack_bf2(sc[2*kc    ][0], sc[2*kc    ][1]);
            af[1] = pack_bf2(sc[2*kc    ][2], sc[2*kc    ][3]);
            af[2] = pack_bf2(sc[2*kc + 1][0], sc[2*kc + 1][1]);
            af[3] = pack_bf2(sc[2*kc + 1][2], sc[2*kc + 1][3]);
#pragma unroll
            for (int nt = 0; nt < 8; nt++) {
                uint32_t bf[2];
                bf[0] = Vs[nt*8 + gid][kc*8 + tig    ];
                bf[1] = Vs[nt*8 + gid][kc*8 + tig + 4];
                mma_bf16(o[nt], af, bf);
            }
        }

        __syncthreads();
        if (j < 15) {
#pragma unroll
            for (int i = 0; i < 4; i++) {
                *(uint4*)&Ks[lr][(lc + i)*4] = kr[i];
                *(uint4*)&Vs[lr][(lc + i)*4] = vr[i];
            }
        }
        __syncthreads();
    }

    const float inv0 = 1.0f / li[0];
    const float inv1 = 1.0f / li[1];
    const int r0 = qt*64 + wq + gid;
    const int r1 = r0 + 8;
#pragma unroll
    for (int nt = 0; nt < 8; nt++) {
        const int col = h*64 + nt*8 + tig*2;
        *(uint32_t*)&g_Ctxb[((size_t)(b*SS + r0))*DD + col] =
            pack_bf2(o[nt][0]*inv0, o[nt][1]*inv0);
        *(uint32_t*)&g_Ctxb[((size_t)(b*SS + r1))*DD + col] =
            pack_bf2(o[nt][2]*inv1, o[nt][3]*inv1);
    }
}

// ---------------------------------------------------------------------------
__global__ void finalize_stats()
{
    const int t = threadIdx.x;
    if (t < BB) {
        double s = 0.0, q = 0.0;
        for (int i = 0; i < 64; i++) {
            s += (double)g_psum[t*64 + i];
            q += (double)g_psq [t*64 + i];
        }
        const double n = (double)NELEM_PER_BATCH;
        const double mean = s / n;
        const double var  = q / n - mean*mean;
        g_mean[t] = (float)mean;
        g_rstd[t] = (float)(1.0 / sqrt(var + 1e-5));
    }
}

__global__ __launch_bounds__(512)
void ln_apply(const float* __restrict__ lnw, const float* __restrict__ lnb,
              float* __restrict__ out)
{
    const size_t i4 = (size_t)blockIdx.x * 512 + threadIdx.x;
    const size_t i  = i4 * 4;
    const int b     = (int)(i >> 20);
    const size_t sd = i & (size_t)(NELEM_PER_BATCH - 1);

    const float4 y = *(const float4*)&g_Y[i];
    const float4 w = *(const float4*)&lnw[sd];
    const float4 c = *(const float4*)&lnb[sd];
    const float mu = g_mean[b];
    const float rs = g_rstd[b];

    float4 r;
    r.x = (y.x - mu)*rs*w.x + c.x;
    r.y = (y.y - mu)*rs*w.y + c.y;
    r.z = (y.z - mu)*rs*w.z + c.z;
    r.w = (y.w - mu)*rs*w.w + c.w;
    *(float4*)&out[i] = r;
}

// ---------------------------------------------------------------------------
extern "C" void kernel_launch(void* const* d_in, const int* in_sizes, int n_in,
                              void* d_out, int out_size)
{
    const float* x   = (const float*)d_in[0];
    const float* Wqk = (const float*)d_in[1];
    const float* bqk = (const float*)d_in[2];
    const float* Wv  = (const float*)d_in[3];
    const float* bv  = (const float*)d_in[4];
    const float* Wo  = (const float*)d_in[5];
    const float* bo  = (const float*)d_in[6];
    const float* lnw = (const float*)d_in[7];
    const float* lnb = (const float*)d_in[8];
    float* out = (float*)d_out;

    __nv_bfloat16 *Xb, *Wqkb, *Wvb, *Wob, *Ctxb;
    cudaGetSymbolAddress((void**)&Xb,   g_Xb);
    cudaGetSymbolAddress((void**)&Wqkb, g_Wqkb);
    cudaGetSymbolAddress((void**)&Wvb,  g_Wvb);
    cudaGetSymbolAddress((void**)&Wob,  g_Wob);
    cudaGetSymbolAddress((void**)&Ctxb, g_Ctxb);

    convertk<<<(MTOT*DD/4)/256, 256>>>(x,   Xb);
    convertk<<<(2048*DD/4)/256, 256>>>(Wqk, Wqkb);
    convertk<<<(1024*DD/4)/256, 256>>>(Wv,  Wvb);
    convertk<<<(1024*DD/4)/256, 256>>>(Wo,  Wob);

    gemm_cp<0><<<dim3(2048/128, MTOT/128), 256>>>(Xb,   Wqkb, bqk, x);  // q,k
    gemm_cp<1><<<dim3(1024/128, MTOT/128), 256>>>(Xb,   Wvb,  bv,  x);  // v
    attn_bf16  <<<dim3(SS/64, HH, BB), 128>>>();                        // ctx
    gemm_cp<2><<<dim3(1024/128, MTOT/128), 256>>>(Ctxb, Wob,  bo,  x);  // y + stats
    finalize_stats<<<1, 32>>>();
    ln_apply<<<(MTOT*DD/4)/512, 512>>>(lnw, lnb, out);
}